// round 2
// baseline (speedup 1.0000x reference)
#include <cuda_runtime.h>
#include <cstdint>
#include <cstddef>

// Problem constants (fixed shapes)
#define SEQ_L   8192
#define DMODEL  1024
#define NBATCH  2
#define NGROUP  256
#define LCACHE  128

// Tiling
#define T_TILE  128
#define NPAIR   16                       // 16 channel pairs = 32 channels per CTA
#define WIN     (T_TILE + LCACHE - 1)    // 255 float2 per z row
#define KSTR    (LCACHE + 1)             // 129 (bank-stagger filter rows)
#define XSTR    (T_TILE + 1)             // 129 (bank-stagger x1 rows)
#define NTHREADS 128

#define SMEM_BYTES ((NPAIR * WIN + NPAIR * XSTR + 8 * KSTR) * (int)sizeof(float2))

// Decayed filter, precomputed once per launch: k[g,tau] = h[g,tau]*exp(-10^(2g/255) * tau/127)
__device__ float g_k[NGROUP * LCACHE];

__global__ void build_filter(const float* __restrict__ h) {
    int g = blockIdx.x;
    int tau = threadIdx.x;
    float decay = exp10f(2.0f * (float)g * (1.0f / 255.0f));
    float t = (float)tau * (1.0f / 127.0f);
    g_k[g * LCACHE + tau] = h[g * LCACHE + tau] * expf(-decay * t);
}

// 64-bit packed fp32 helpers (Blackwell f32x2 pipe: 2 FMA per FFMA2 issue)
__device__ __forceinline__ unsigned long long ld2(const float2* p) {
    return *reinterpret_cast<const unsigned long long*>(p);
}
__device__ __forceinline__ void fma2(unsigned long long& d, unsigned long long a, unsigned long long b) {
    asm("fma.rn.f32x2 %0, %1, %2, %0;" : "+l"(d) : "l"(a), "l"(b));
}
__device__ __forceinline__ void mul2(unsigned long long& d, unsigned long long a) {
    asm("mul.rn.f32x2 %0, %0, %1;" : "+l"(d) : "l"(a));
}

__global__ __launch_bounds__(NTHREADS) void hyena_main(
    const float* __restrict__ x1g, const float* __restrict__ x2g,
    const float* __restrict__ vg,  const float* __restrict__ biasg,
    float* __restrict__ outg)
{
    extern __shared__ float2 sm[];
    float2* z_sh  = sm;                    // [NPAIR][WIN]   interleaved channel pairs
    float2* x1_sh = z_sh + NPAIR * WIN;    // [NPAIR][XSTR]
    float2* k_sh  = x1_sh + NPAIR * XSTR;  // [8][KSTR]      duplicated (k,k) per group

    const int tid   = threadIdx.x;
    const int b     = blockIdx.z;
    const int dblk  = blockIdx.y;                 // 0..31
    const int t0    = blockIdx.x * T_TILE;        // 0..8064
    const int dbase = dblk * (2 * NPAIR);         // 32 channels per block

    // ---- stage filter: 8 groups x 128 taps, duplicated into float2 ----
    {
        const int gbase = dbase >> 2;             // group = d/4
        for (int i = tid; i < 8 * LCACHE; i += NTHREADS) {
            int gl = i >> 7, tau = i & 127;
            float kv = g_k[(gbase + gl) * LCACHE + tau];
            k_sh[gl * KSTR + tau] = make_float2(kv, kv);
        }
    }

    // ---- stage z = x2*v (with 127 halo, zero before t=0) and x1 tile ----
    {
        const int wid = tid >> 5, lane = tid & 31;
        for (int c = 0; c < 8; ++c) {
            const int ch = wid * 8 + c;           // 0..31 local channel
            const int d  = dbase + ch;
            const size_t rowoff = ((size_t)b * DMODEL + d) * SEQ_L;
            const float* px2 = x2g + rowoff;
            const float* pv  = vg  + rowoff;
            const float* px1 = x1g + rowoff;
            const int pair = ch >> 1, comp = ch & 1;
            float* zr = reinterpret_cast<float*>(z_sh + pair * WIN) + comp;
            float* xr = reinterpret_cast<float*>(x1_sh + pair * XSTR) + comp;
            for (int i = lane; i < WIN; i += 32) {
                int tg = t0 - (LCACHE - 1) + i;
                float zv = 0.0f;
                if (tg >= 0) zv = px2[tg] * pv[tg];
                zr[2 * i] = zv;
            }
            for (int i = lane; i < T_TILE; i += 32)
                xr[2 * i] = px1[t0 + i];
        }
    }
    __syncthreads();

    // ---- compute: each thread owns 1 channel pair x 16 timesteps ----
    const int pair   = tid & 15;
    const int tslice = tid >> 4;                  // 0..7
    const int tb_loc = (LCACHE - 1) + tslice * 16; // local z index of first output t
    const float2* krow = k_sh + (pair >> 1) * KSTR;
    const float2* zrow = z_sh + pair * WIN;

    unsigned long long acc[16];
    #pragma unroll
    for (int j = 0; j < 16; ++j) acc[j] = 0ull;   // packed (0.f, 0.f)

    // sliding window: r[i] = z[tb_loc - tau0 - 7 + i], covers 8 taus x 16 t
    unsigned long long r[23];
    #pragma unroll
    for (int i = 0; i < 23; ++i) r[i] = ld2(zrow + (tb_loc - 127 + i));

    #pragma unroll
    for (int grp = 0; grp < 16; ++grp) {
        const int tau0 = 120 - grp * 8;
        #pragma unroll
        for (int dt = 0; dt < 8; ++dt) {
            unsigned long long kk = ld2(krow + (tau0 + dt));
            #pragma unroll
            for (int j = 0; j < 16; ++j)
                fma2(acc[j], kk, r[7 - dt + j]);
        }
        if (grp < 15) {
            #pragma unroll
            for (int i = 0; i < 15; ++i) r[i] = r[i + 8];
            #pragma unroll
            for (int m = 0; m < 8; ++m)
                r[15 + m] = ld2(zrow + (tb_loc - tau0 + 16 + m));
        }
    }

    // ---- epilogue: out = (y + z*bias) * x1, store transposed [B,L,D] ----
    const int d0 = dbase + pair * 2;
    const float2 bb = *reinterpret_cast<const float2*>(biasg + d0);
    const unsigned long long bpk = *reinterpret_cast<const unsigned long long*>(&bb);
    float* op = outg + ((size_t)b * SEQ_L + (size_t)(t0 + tslice * 16)) * DMODEL + d0;
    #pragma unroll
    for (int j = 0; j < 16; ++j) {
        unsigned long long zt = ld2(zrow + (tb_loc + j));
        fma2(acc[j], zt, bpk);                         // y + z*bias
        unsigned long long xx = ld2(x1_sh + pair * XSTR + tslice * 16 + j);
        mul2(acc[j], xx);                              // * x1
        *reinterpret_cast<unsigned long long*>(op + (size_t)j * DMODEL) = acc[j];
    }
}

extern "C" void kernel_launch(void* const* d_in, const int* in_sizes, int n_in,
                              void* d_out, int out_size) {
    const float* x1 = (const float*)d_in[0];
    const float* x2 = (const float*)d_in[1];
    const float* v  = (const float*)d_in[2];
    const float* h  = (const float*)d_in[3];
    const float* cb = (const float*)d_in[4];
    float* out = (float*)d_out;

    cudaFuncSetAttribute(hyena_main, cudaFuncAttributeMaxDynamicSharedMemorySize, SMEM_BYTES);

    build_filter<<<NGROUP, LCACHE>>>(h);

    dim3 grid(SEQ_L / T_TILE, DMODEL / (2 * NPAIR), NBATCH);  // (64, 32, 2)
    hyena_main<<<grid, NTHREADS, SMEM_BYTES>>>(x1, x2, v, cb, out);
}

// round 3
// speedup vs baseline: 2.8127x; 2.8127x over previous
#include <cuda_runtime.h>
#include <cstdint>
#include <cstddef>

// Problem constants (fixed shapes)
#define SEQ_L   8192
#define DMODEL  1024
#define NBATCH  2
#define NGROUP  256
#define LCACHE  128

// Tiling
#define T_TILE  128
#define NPAIR   16                       // 16 channel pairs = 32 channels per CTA
#define WIN     256                      // z window [t0-128, t0+128), outputs at i in [128,256)
#define ZSTR    257                      // padded row stride (float2) -> conflict-free LDS
#define KSTR    (LCACHE + 1)             // 129
#define NTHREADS 128

#define SMEM_BYTES ((NPAIR * ZSTR + 8 * KSTR) * (int)sizeof(float2))

// Decayed filter, precomputed once per launch: k[g,tau] = h[g,tau]*exp(-10^(2g/255) * tau/127)
__device__ float g_k[NGROUP * LCACHE];

__global__ void build_filter(const float* __restrict__ h) {
    int g = blockIdx.x;
    int tau = threadIdx.x;
    float decay = exp10f(2.0f * (float)g * (1.0f / 255.0f));
    float t = (float)tau * (1.0f / 127.0f);
    g_k[g * LCACHE + tau] = h[g * LCACHE + tau] * expf(-decay * t);
}

// 64-bit packed fp32 helpers (Blackwell f32x2: 2 FMA lanes per issue)
__device__ __forceinline__ unsigned long long ld2(const float2* p) {
    return *reinterpret_cast<const unsigned long long*>(p);
}
__device__ __forceinline__ void fma2(unsigned long long& d, unsigned long long a, unsigned long long b) {
    asm("fma.rn.f32x2 %0, %1, %2, %0;" : "+l"(d) : "l"(a), "l"(b));
}

__global__ __launch_bounds__(NTHREADS, 5) void hyena_main(
    const float* __restrict__ x1g, const float* __restrict__ x2g,
    const float* __restrict__ vg,  const float* __restrict__ biasg,
    float* __restrict__ outg)
{
    extern __shared__ float2 sm[];
    float2* z_sh = sm;                    // [NPAIR][ZSTR] interleaved channel pairs
    float2* k_sh = z_sh + NPAIR * ZSTR;   // [8][KSTR]     duplicated (k,k) per group

    const int tid   = threadIdx.x;
    const int b     = blockIdx.z;
    const int dblk  = blockIdx.y;                 // 0..31
    const int t0    = blockIdx.x * T_TILE;        // 0..8064
    const int dbase = dblk * (2 * NPAIR);         // 32 channels per block

    // ---- stage filter: 8 groups x 128 taps, duplicated into float2 ----
    {
        const int gbase = dbase >> 2;             // group = d/4
        for (int i = tid; i < 8 * LCACHE; i += NTHREADS) {
            int gl = i >> 7, tau = i & 127;
            float kv = g_k[(gbase + gl) * LCACHE + tau];
            k_sh[gl * KSTR + tau] = make_float2(kv, kv);
        }
    }

    // ---- stage z = x2*v for window [t0-128, t0+128), float4 loads, high MLP ----
    {
        const int p = tid >> 3;                   // pair 0..15
        const int s = tid & 7;                    // 8 threads per pair
        const int d0 = dbase + 2 * p;
        const size_t r0 = ((size_t)b * DMODEL + d0) * SEQ_L;
        const size_t r1 = r0 + SEQ_L;
        float2* zrow = z_sh + p * ZSTR;
        #pragma unroll 4
        for (int c = 0; c < 8; ++c) {
            const int idx = c * 8 + s;            // float4 index 0..63 (lanes coalesced)
            const int tg  = t0 - 128 + 4 * idx;
            float4 a0, a1, v0, v1;
            if (tg >= 0) {
                a0 = *reinterpret_cast<const float4*>(x2g + r0 + tg);
                a1 = *reinterpret_cast<const float4*>(x2g + r1 + tg);
                v0 = *reinterpret_cast<const float4*>(vg  + r0 + tg);
                v1 = *reinterpret_cast<const float4*>(vg  + r1 + tg);
            } else {
                a0 = a1 = v0 = v1 = make_float4(0.f, 0.f, 0.f, 0.f);
            }
            float2* zp = zrow + 4 * idx;
            zp[0] = make_float2(a0.x * v0.x, a1.x * v1.x);
            zp[1] = make_float2(a0.y * v0.y, a1.y * v1.y);
            zp[2] = make_float2(a0.z * v0.z, a1.z * v1.z);
            zp[3] = make_float2(a0.w * v0.w, a1.w * v1.w);
        }
    }
    __syncthreads();

    // ---- compute: each thread owns 1 channel pair x 16 timesteps ----
    const int pair   = tid & 15;
    const int tslice = tid >> 4;                   // 0..7
    const int tb_loc = 128 + tslice * 16;          // local z index of first output t
    const float2* krow = k_sh + (pair >> 1) * KSTR;
    const float2* zrow = z_sh + pair * ZSTR;

    unsigned long long acc[16];
    #pragma unroll
    for (int j = 0; j < 16; ++j) acc[j] = 0ull;    // packed (0.f, 0.f)

    // sliding window: r[i] = z[tb_loc - 127 + i] initially; covers 8 taps x 16 t per grp
    unsigned long long r[23];
    #pragma unroll
    for (int i = 0; i < 23; ++i) r[i] = ld2(zrow + (tb_loc - 127 + i));

    #pragma unroll
    for (int grp = 0; grp < 16; ++grp) {
        const int tau0 = 120 - grp * 8;
        #pragma unroll
        for (int dt = 0; dt < 8; ++dt) {
            unsigned long long kk = ld2(krow + (tau0 + dt));
            #pragma unroll
            for (int j = 0; j < 16; ++j)
                fma2(acc[j], kk, r[7 - dt + j]);
        }
        if (grp < 15) {
            #pragma unroll
            for (int i = 0; i < 15; ++i) r[i] = r[i + 8];
            #pragma unroll
            for (int m = 0; m < 8; ++m)
                r[15 + m] = ld2(zrow + (tb_loc - tau0 + 16 + m));
        }
    }

    // ---- epilogue: out = (y + z*bias) * x1, x1 straight from global ----
    const int d0e = dbase + pair * 2;
    const float2 bb = *reinterpret_cast<const float2*>(biasg + d0e);
    const unsigned long long bpk = *reinterpret_cast<const unsigned long long*>(&bb);

    const float* x1r0 = x1g + ((size_t)b * DMODEL + d0e) * SEQ_L + t0 + tslice * 16;
    const float* x1r1 = x1r0 + SEQ_L;
    float4 xa[4], xb[4];
    #pragma unroll
    for (int q = 0; q < 4; ++q) {
        xa[q] = *reinterpret_cast<const float4*>(x1r0 + 4 * q);
        xb[q] = *reinterpret_cast<const float4*>(x1r1 + 4 * q);
    }

    float* op = outg + ((size_t)b * SEQ_L + (size_t)(t0 + tslice * 16)) * DMODEL + d0e;
    #pragma unroll
    for (int j = 0; j < 16; ++j) {
        unsigned long long zt = ld2(zrow + (tb_loc + j));
        fma2(acc[j], zt, bpk);                          // y + z*bias
        float2 res = *reinterpret_cast<float2*>(&acc[j]);
        const float* pxa = reinterpret_cast<const float*>(&xa[j >> 2]);
        const float* pxb = reinterpret_cast<const float*>(&xb[j >> 2]);
        res.x *= pxa[j & 3];
        res.y *= pxb[j & 3];
        *reinterpret_cast<float2*>(op + (size_t)j * DMODEL) = res;
    }
}

extern "C" void kernel_launch(void* const* d_in, const int* in_sizes, int n_in,
                              void* d_out, int out_size) {
    const float* x1 = (const float*)d_in[0];
    const float* x2 = (const float*)d_in[1];
    const float* v  = (const float*)d_in[2];
    const float* h  = (const float*)d_in[3];
    const float* cb = (const float*)d_in[4];
    float* out = (float*)d_out;

    cudaFuncSetAttribute(hyena_main, cudaFuncAttributeMaxDynamicSharedMemorySize, SMEM_BYTES);

    build_filter<<<NGROUP, LCACHE>>>(h);

    dim3 grid(SEQ_L / T_TILE, DMODEL / (2 * NPAIR), NBATCH);  // (64, 32, 2)
    hyena_main<<<grid, NTHREADS, SMEM_BYTES>>>(x1, x2, v, cb, out);
}

// round 4
// speedup vs baseline: 2.9059x; 1.0331x over previous
#include <cuda_runtime.h>
#include <cstdint>
#include <cstddef>

// Problem constants (fixed shapes)
#define SEQ_L   8192
#define DMODEL  1024
#define NBATCH  2
#define NGROUP  256
#define LCACHE  128

// Tiling
#define T_TILE  128
#define NPAIR   16                       // 16 channel pairs = 32 channels per CTA
#define WIN     256                      // z window [t0-128, t0+128)
#define ZSTR    257                      // padded row stride (float2) -> conflict-free LDS
#define KSTRF   129                      // scalar filter row stride (floats)
#define NTHREADS 128

#define SMEM_BYTES (NPAIR * ZSTR * (int)sizeof(float2) + 8 * KSTRF * (int)sizeof(float))

// Decayed filter, precomputed once per launch: k[g,tau] = h[g,tau]*exp(-10^(2g/255) * tau/127)
__device__ float g_k[NGROUP * LCACHE];

__global__ void build_filter(const float* __restrict__ h) {
    int g = blockIdx.x;
    int tau = threadIdx.x;
    float decay = exp10f(2.0f * (float)g * (1.0f / 255.0f));
    float t = (float)tau * (1.0f / 127.0f);
    g_k[g * LCACHE + tau] = h[g * LCACHE + tau] * expf(-decay * t);
}

// 64-bit packed fp32 helpers (f32x2: 2 FMA lanes per issue)
__device__ __forceinline__ unsigned long long ld2(const float2* p) {
    return *reinterpret_cast<const unsigned long long*>(p);
}
__device__ __forceinline__ void fma2(unsigned long long& d, unsigned long long a, unsigned long long b) {
    asm("fma.rn.f32x2 %0, %1, %2, %0;" : "+l"(d) : "l"(a), "l"(b));
}
__device__ __forceinline__ unsigned long long pack2(float v) {
    unsigned long long d;
    asm("mov.b64 %0, {%1, %1};" : "=l"(d) : "f"(v));
    return d;
}

__global__ __launch_bounds__(NTHREADS, 6) void hyena_main(
    const float* __restrict__ x1g, const float* __restrict__ x2g,
    const float* __restrict__ vg,  const float* __restrict__ biasg,
    float* __restrict__ outg)
{
    extern __shared__ float2 sm[];
    float2* z_sh = sm;                                          // [NPAIR][ZSTR]
    float*  k_sh = reinterpret_cast<float*>(z_sh + NPAIR * ZSTR); // [8][KSTRF] scalar taps

    const int tid   = threadIdx.x;
    const int b     = blockIdx.z;
    const int dblk  = blockIdx.y;                 // 0..31
    const int t0    = blockIdx.x * T_TILE;        // 0..8064
    const int dbase = dblk * (2 * NPAIR);         // 32 channels per block

    // ---- stage filter: 8 groups x 128 taps (scalar) ----
    {
        const int gbase = dbase >> 2;             // group = d/4
        for (int i = tid; i < 8 * LCACHE; i += NTHREADS) {
            int gl = i >> 7, tau = i & 127;
            k_sh[gl * KSTRF + tau] = g_k[(gbase + gl) * LCACHE + tau];
        }
    }

    // ---- stage z = x2*v for window [t0-128, t0+128), float4 loads, high MLP ----
    {
        const int p = tid >> 3;                   // pair 0..15
        const int s = tid & 7;                    // 8 threads per pair
        const int d0 = dbase + 2 * p;
        const size_t r0 = ((size_t)b * DMODEL + d0) * SEQ_L;
        const size_t r1 = r0 + SEQ_L;
        float2* zrow = z_sh + p * ZSTR;
        #pragma unroll 4
        for (int c = 0; c < 8; ++c) {
            const int idx = c * 8 + s;            // float4 index 0..63
            const int tg  = t0 - 128 + 4 * idx;
            float4 a0, a1, v0, v1;
            if (tg >= 0) {
                a0 = *reinterpret_cast<const float4*>(x2g + r0 + tg);
                a1 = *reinterpret_cast<const float4*>(x2g + r1 + tg);
                v0 = *reinterpret_cast<const float4*>(vg  + r0 + tg);
                v1 = *reinterpret_cast<const float4*>(vg  + r1 + tg);
            } else {
                a0 = a1 = v0 = v1 = make_float4(0.f, 0.f, 0.f, 0.f);
            }
            float2* zp = zrow + 4 * idx;
            zp[0] = make_float2(a0.x * v0.x, a1.x * v1.x);
            zp[1] = make_float2(a0.y * v0.y, a1.y * v1.y);
            zp[2] = make_float2(a0.z * v0.z, a1.z * v1.z);
            zp[3] = make_float2(a0.w * v0.w, a1.w * v1.w);
        }
    }
    __syncthreads();

    // ---- compute: each thread owns 1 channel pair x 16 timesteps ----
    const int pair   = tid & 15;
    const int tslice = tid >> 4;                   // 0..7
    const int tb_loc = 128 + tslice * 16;          // local z index of first output t
    const float*  krow = k_sh + (pair >> 1) * KSTRF;
    const float2* zrow = z_sh + pair * ZSTR;
    const float2* zbase = zrow + (tb_loc - 127);   // abs index 0 of window

    unsigned long long acc[16];
    #pragma unroll
    for (int j = 0; j < 16; ++j) acc[j] = 0ull;

    // circular register window over 20 slots; abs a -> slot a%20.
    // grp g (4 taps, tau = 127-(4g+dt)) touches abs [4g, 4g+18].
    unsigned long long r[20];
    #pragma unroll
    for (int i = 0; i < 19; ++i) r[i] = ld2(zbase + i);

    #pragma unroll
    for (int g = 0; g < 32; ++g) {
        #pragma unroll
        for (int dt = 0; dt < 4; ++dt) {
            const int tau = 127 - (4 * g + dt);
            unsigned long long kk = pack2(krow[tau]);
            #pragma unroll
            for (int j = 0; j < 16; ++j)
                fma2(acc[j], kk, r[(4 * g + dt + j) % 20]);
        }
        if (g < 31) {
            #pragma unroll
            for (int m = 0; m < 4; ++m) {
                const int a = 4 * g + 19 + m;
                r[a % 20] = ld2(zbase + a);
            }
        }
    }

    // ---- epilogue: out = (y + z*bias) * x1, x1 straight from global ----
    const int d0e = dbase + pair * 2;
    const float2 bb = *reinterpret_cast<const float2*>(biasg + d0e);
    const unsigned long long bpk = *reinterpret_cast<const unsigned long long*>(&bb);

    const float* x1r0 = x1g + ((size_t)b * DMODEL + d0e) * SEQ_L + t0 + tslice * 16;
    const float* x1r1 = x1r0 + SEQ_L;
    float4 xa[4], xb[4];
    #pragma unroll
    for (int q = 0; q < 4; ++q) {
        xa[q] = *reinterpret_cast<const float4*>(x1r0 + 4 * q);
        xb[q] = *reinterpret_cast<const float4*>(x1r1 + 4 * q);
    }

    float* op = outg + ((size_t)b * SEQ_L + (size_t)(t0 + tslice * 16)) * DMODEL + d0e;
    #pragma unroll
    for (int j = 0; j < 16; ++j) {
        unsigned long long zt = ld2(zrow + (tb_loc + j));
        fma2(acc[j], zt, bpk);                          // y + z*bias
        float2 res = *reinterpret_cast<float2*>(&acc[j]);
        const float* pxa = reinterpret_cast<const float*>(&xa[j >> 2]);
        const float* pxb = reinterpret_cast<const float*>(&xb[j >> 2]);
        res.x *= pxa[j & 3];
        res.y *= pxb[j & 3];
        *reinterpret_cast<float2*>(op + (size_t)j * DMODEL) = res;
    }
}

extern "C" void kernel_launch(void* const* d_in, const int* in_sizes, int n_in,
                              void* d_out, int out_size) {
    const float* x1 = (const float*)d_in[0];
    const float* x2 = (const float*)d_in[1];
    const float* v  = (const float*)d_in[2];
    const float* h  = (const float*)d_in[3];
    const float* cb = (const float*)d_in[4];
    float* out = (float*)d_out;

    cudaFuncSetAttribute(hyena_main, cudaFuncAttributeMaxDynamicSharedMemorySize, SMEM_BYTES);

    build_filter<<<NGROUP, LCACHE>>>(h);

    dim3 grid(SEQ_L / T_TILE, DMODEL / (2 * NPAIR), NBATCH);  // (64, 32, 2)
    hyena_main<<<grid, NTHREADS, SMEM_BYTES>>>(x1, x2, v, cb, out);
}

// round 6
// speedup vs baseline: 2.9586x; 1.0181x over previous
#include <cuda_runtime.h>
#include <cstdint>
#include <cstddef>

// Problem constants (fixed shapes)
#define SEQ_L   8192
#define DMODEL  1024
#define NBATCH  2
#define NGROUP  256
#define LCACHE  128

// Tiling
#define T_TILE  128
#define NPAIR   16                       // 16 channel pairs = 32 channels per CTA
#define ZSTR    257                      // padded row stride (float2) -> conflict-free LDS
#define KSTRF   132                      // filter row stride in floats (16B-aligned rows)
#define NTHREADS 128

#define SMEM_BYTES (NPAIR * ZSTR * (int)sizeof(float2) + 8 * KSTRF * (int)sizeof(float))

// Decayed filter, precomputed once per launch: k[g,tau] = h[g,tau]*exp(-10^(2g/255) * tau/127)
__device__ float g_k[NGROUP * LCACHE];

__global__ void build_filter(const float* __restrict__ h) {
    int g = blockIdx.x;
    int tau = threadIdx.x;
    float decay = exp10f(2.0f * (float)g * (1.0f / 255.0f));
    float t = (float)tau * (1.0f / 127.0f);
    g_k[g * LCACHE + tau] = h[g * LCACHE + tau] * expf(-decay * t);
}

// 64-bit packed fp32 helpers (f32x2: 2 FMA lanes per issue)
__device__ __forceinline__ unsigned long long ld2(const float2* p) {
    return *reinterpret_cast<const unsigned long long*>(p);
}
__device__ __forceinline__ void fma2(unsigned long long& d, unsigned long long a, unsigned long long b) {
    asm("fma.rn.f32x2 %0, %1, %2, %0;" : "+l"(d) : "l"(a), "l"(b));
}
__device__ __forceinline__ unsigned long long pack2(float v) {
    unsigned long long d;
    asm("mov.b64 %0, {%1, %1};" : "=l"(d) : "f"(v));
    return d;
}

__global__ __launch_bounds__(NTHREADS, 6) void hyena_main(
    const float* __restrict__ x1g, const float* __restrict__ x2g,
    const float* __restrict__ vg,  const float* __restrict__ biasg,
    float* __restrict__ outg)
{
    extern __shared__ float2 sm[];
    float2* z_sh = sm;                                            // [NPAIR][ZSTR]
    float*  k_sh = reinterpret_cast<float*>(z_sh + NPAIR * ZSTR); // [8][KSTRF]

    const int tid   = threadIdx.x;
    const int b     = blockIdx.z;
    const int dblk  = blockIdx.y;                 // 0..31
    const int t0    = blockIdx.x * T_TILE;        // 0..8064
    const int dbase = dblk * (2 * NPAIR);         // 32 channels per block

    // ---- stage filter: 8 groups x 128 taps (scalar, 16B-aligned rows) ----
    {
        const int gbase = dbase >> 2;             // group = d/4
        for (int i = tid; i < 8 * LCACHE; i += NTHREADS) {
            int gl = i >> 7, tau = i & 127;
            k_sh[gl * KSTRF + tau] = g_k[(gbase + gl) * LCACHE + tau];
        }
    }

    // ---- stage z = x2*v for window [t0-128, t0+128), float4 loads, high MLP ----
    {
        const int p = tid >> 3;                   // pair 0..15
        const int s = tid & 7;                    // 8 threads per pair
        const int d0 = dbase + 2 * p;
        const size_t r0 = ((size_t)b * DMODEL + d0) * SEQ_L;
        const size_t r1 = r0 + SEQ_L;
        float2* zrow = z_sh + p * ZSTR;
        #pragma unroll 4
        for (int c = 0; c < 8; ++c) {
            const int idx = c * 8 + s;            // float4 index 0..63
            const int tg  = t0 - 128 + 4 * idx;
            float4 a0, a1, v0, v1;
            if (tg >= 0) {
                a0 = *reinterpret_cast<const float4*>(x2g + r0 + tg);
                a1 = *reinterpret_cast<const float4*>(x2g + r1 + tg);
                v0 = *reinterpret_cast<const float4*>(vg  + r0 + tg);
                v1 = *reinterpret_cast<const float4*>(vg  + r1 + tg);
            } else {
                a0 = a1 = v0 = v1 = make_float4(0.f, 0.f, 0.f, 0.f);
            }
            float2* zp = zrow + 4 * idx;
            zp[0] = make_float2(a0.x * v0.x, a1.x * v1.x);
            zp[1] = make_float2(a0.y * v0.y, a1.y * v1.y);
            zp[2] = make_float2(a0.z * v0.z, a1.z * v1.z);
            zp[3] = make_float2(a0.w * v0.w, a1.w * v1.w);
        }
    }
    __syncthreads();

    // ---- compute: each thread owns 1 channel pair x 16 timesteps ----
    const int pair   = tid & 15;
    const int tslice = tid >> 4;                   // 0..7
    const int tb_loc = 128 + tslice * 16;          // local z index of first output t
    const float*  krow = k_sh + (pair >> 1) * KSTRF;
    const float2* zrow = z_sh + pair * ZSTR;
    const float2* zbase = zrow + (tb_loc - 127);   // abs index 0 of window

    unsigned long long acc[16];
    #pragma unroll
    for (int j = 0; j < 16; ++j) acc[j] = 0ull;

    // circular register window over 20 slots; abs a -> slot a%20.
    // group g handles taps tau = 127-(4g+dt), reading abs [4g, 4g+18].
    // REFILL MUST FOLLOW COMPUTE: abs 4g+20 maps to the same slot as abs 4g.
    unsigned long long r[20];
    #pragma unroll
    for (int i = 0; i < 19; ++i) r[i] = ld2(zbase + i);

    #pragma unroll
    for (int g = 0; g < 32; ++g) {
        // 4 taps per group, one LDS.128: taus 124-4g .. 127-4g
        const float4 kq = *reinterpret_cast<const float4*>(krow + (124 - 4 * g));
        // dt=0 -> tau=127-4g = kq.w ; dt=1 -> .z ; dt=2 -> .y ; dt=3 -> .x
        {
            const unsigned long long kk = pack2(kq.w);
            #pragma unroll
            for (int j = 0; j < 16; ++j) fma2(acc[j], kk, r[(4 * g + 0 + j) % 20]);
        }
        {
            const unsigned long long kk = pack2(kq.z);
            #pragma unroll
            for (int j = 0; j < 16; ++j) fma2(acc[j], kk, r[(4 * g + 1 + j) % 20]);
        }
        {
            const unsigned long long kk = pack2(kq.y);
            #pragma unroll
            for (int j = 0; j < 16; ++j) fma2(acc[j], kk, r[(4 * g + 2 + j) % 20]);
        }
        {
            const unsigned long long kk = pack2(kq.x);
            #pragma unroll
            for (int j = 0; j < 16; ++j) fma2(acc[j], kk, r[(4 * g + 3 + j) % 20]);
        }
        // refill for next group (consumed >=16 FMA issues later -> latency hidden)
        if (g < 31) {
            #pragma unroll
            for (int m = 0; m < 4; ++m) {
                const int a = 4 * g + 19 + m;
                r[a % 20] = ld2(zbase + a);
            }
        }
    }

    // ---- epilogue: out = (y + z*bias) * x1 ----
    // window now holds abs 123..142 = z[tb_loc-4 .. tb_loc+15]; zt(j) = abs 127+j
    const int d0e = dbase + pair * 2;
    const float2 bb = *reinterpret_cast<const float2*>(biasg + d0e);
    const unsigned long long bpk = *reinterpret_cast<const unsigned long long*>(&bb);

    const float* x1r0 = x1g + ((size_t)b * DMODEL + d0e) * SEQ_L + t0 + tslice * 16;
    const float* x1r1 = x1r0 + SEQ_L;
    float4 xa[4], xb[4];
    #pragma unroll
    for (int q = 0; q < 4; ++q) {
        xa[q] = *reinterpret_cast<const float4*>(x1r0 + 4 * q);
        xb[q] = *reinterpret_cast<const float4*>(x1r1 + 4 * q);
    }

    float* op = outg + ((size_t)b * SEQ_L + (size_t)(t0 + tslice * 16)) * DMODEL + d0e;
    #pragma unroll
    for (int j = 0; j < 16; ++j) {
        const unsigned long long zt = r[(127 + j) % 20];
        fma2(acc[j], zt, bpk);                          // y + z*bias
        float2 res = *reinterpret_cast<float2*>(&acc[j]);
        const float* pxa = reinterpret_cast<const float*>(&xa[j >> 2]);
        const float* pxb = reinterpret_cast<const float*>(&xb[j >> 2]);
        res.x *= pxa[j & 3];
        res.y *= pxb[j & 3];
        *reinterpret_cast<float2*>(op + (size_t)j * DMODEL) = res;
    }
}

extern "C" void kernel_launch(void* const* d_in, const int* in_sizes, int n_in,
                              void* d_out, int out_size) {
    const float* x1 = (const float*)d_in[0];
    const float* x2 = (const float*)d_in[1];
    const float* v  = (const float*)d_in[2];
    const float* h  = (const float*)d_in[3];
    const float* cb = (const float*)d_in[4];
    float* out = (float*)d_out;

    cudaFuncSetAttribute(hyena_main, cudaFuncAttributeMaxDynamicSharedMemorySize, SMEM_BYTES);

    build_filter<<<NGROUP, LCACHE>>>(h);

    dim3 grid(SEQ_L / T_TILE, DMODEL / (2 * NPAIR), NBATCH);  // (64, 32, 2)
    hyena_main<<<grid, NTHREADS, SMEM_BYTES>>>(x1, x2, v, cb, out);
}